// round 1
// baseline (speedup 1.0000x reference)
#include <cuda_runtime.h>
#include <math.h>

namespace {

constexpr int Hd = 512;
constexpr int Wd = 512;
constexpr int Cd = 8;
constexpr int Bd = 16;
constexpr int NSTRIP = 8;          // W strips
constexpr int TWp = Wd / NSTRIP;   // 64 pixels per strip
constexpr int HSr = 128;           // output rows per block
constexpr int RS = Wd * Cd;        // 4096 floats per image row
constexpr int THREADS = TWp * Cd / 2;  // 256 threads: one float2 column each

template <bool INTERIOR>
__device__ __forceinline__ void run_strip(const float* __restrict__ in,
                                          float* __restrict__ out,
                                          int strip) {
    const int t  = threadIdx.x;
    const int p  = t >> 2;   // pixel within strip (0..63)
    const int c2 = t & 3;    // float2 slot within channels (0..3)
    const int w  = strip * TWp + p;
    const int h0 = blockIdx.y * HSr;
    const int b  = blockIdx.z;

    const float* colbase = in  + (size_t)b * Hd * RS + w * Cd + c2 * 2;
    float*       obase   = out + (size_t)b * Hd * RS + w * Cd + c2 * 2;

    // Boundary (w-edge) masks + clamped offsets. Interior: compile-time.
    float msk[11];
    int   off[11];
    if (!INTERIOR) {
#pragma unroll
        for (int k = 0; k < 11; ++k) {
            const int ww = w + (k - 5);
            const bool ok = (ww >= 0) && (ww < Wd);
            msk[k] = ok ? 1.0f : 0.0f;
            off[k] = ok ? (k - 5) * Cd : 0;
        }
    }

    // 11-deep register rings of horizontal filter outputs
    float2 Rr[11], Tr[11], Ur[11];
#pragma unroll
    for (int k = 0; k < 11; ++k) {
        Rr[k] = make_float2(0.f, 0.f);
        Tr[k] = make_float2(0.f, 0.f);
        Ur[k] = make_float2(0.f, 0.f);
    }
    // Sliding vertical sums: A = sum R, Bv = sum dh*R, Cv = sum dh^2*R,
    // OY = sum T, SY = sum U  (over the current 11-row window)
    float2 A  = make_float2(0.f, 0.f);
    float2 Bv = make_float2(0.f, 0.f);
    float2 Cv = make_float2(0.f, 0.f);
    float2 OY = make_float2(0.f, 0.f);
    float2 SY = make_float2(0.f, 0.f);

    auto step = [&](int hin, bool emit) {
        float2 Rn = make_float2(0.f, 0.f);
        float2 Tn = make_float2(0.f, 0.f);
        float2 Un = make_float2(0.f, 0.f);
        if (hin >= 0 && hin < Hd) {
            const float* rp = colbase + (size_t)hin * RS;
#pragma unroll
            for (int k = 0; k < 11; ++k) {
                const float dw  = (float)(k - 5);
                const float dw2 = dw * dw;
                const int   o   = INTERIOR ? (k - 5) * Cd : off[k];
                float2 v = *reinterpret_cast<const float2*>(rp + o);
                float2 vm;
                if (INTERIOR) {
                    vm = v;
                } else {
                    vm.x = v.x * msk[k];
                    vm.y = v.y * msk[k];
                }
                Rn.x += vm.x;
                Rn.y += vm.y;
                if (k != 5) {  // dw == 0 contributes nothing to T/U
                    Tn.x = __fmaf_rn(vm.x, dw,  Tn.x);
                    Tn.y = __fmaf_rn(vm.y, dw,  Tn.y);
                    Un.x = __fmaf_rn(vm.x, dw2, Un.x);
                    Un.y = __fmaf_rn(vm.y, dw2, Un.y);
                }
            }
        }

        // Oldest ring entries (row hin-11, leaving the window)
        const float2 Ro = Rr[0];
        const float2 To = Tr[0];
        const float2 Uo = Ur[0];

        // Exact incremental slide (uses OLD A, Bv):
        //   C' = C - 2B + A - 36*R_old + 25*R_new
        //   B' = B - A + 6*R_old + 5*R_new
        //   A' = A - R_old + R_new
        float2 Cn, Bn, An;
        Cn.x = __fmaf_rn(Bv.x, -2.f, Cv.x) + A.x;
        Cn.x = __fmaf_rn(Ro.x, -36.f, Cn.x);
        Cn.x = __fmaf_rn(Rn.x,  25.f, Cn.x);
        Cn.y = __fmaf_rn(Bv.y, -2.f, Cv.y) + A.y;
        Cn.y = __fmaf_rn(Ro.y, -36.f, Cn.y);
        Cn.y = __fmaf_rn(Rn.y,  25.f, Cn.y);

        Bn.x = Bv.x - A.x;
        Bn.x = __fmaf_rn(Ro.x, 6.f, Bn.x);
        Bn.x = __fmaf_rn(Rn.x, 5.f, Bn.x);
        Bn.y = Bv.y - A.y;
        Bn.y = __fmaf_rn(Ro.y, 6.f, Bn.y);
        Bn.y = __fmaf_rn(Rn.y, 5.f, Bn.y);

        An.x = (A.x - Ro.x) + Rn.x;
        An.y = (A.y - Ro.y) + Rn.y;

        OY.x += Tn.x - To.x;
        OY.y += Tn.y - To.y;
        SY.x += Un.x - Uo.x;
        SY.y += Un.y - Uo.y;

        A = An; Bv = Bn; Cv = Cn;

        // Shift rings (register-renamed under unroll)
#pragma unroll
        for (int k = 0; k < 10; ++k) {
            Rr[k] = Rr[k + 1];
            Tr[k] = Tr[k + 1];
            Ur[k] = Ur[k + 1];
        }
        Rr[10] = Rn; Tr[10] = Tn; Ur[10] = Un;

        if (emit) {
            const int h = hin - 5;
            const float n2x = __fmaf_rn(Bv.x, Bv.x, OY.x * OY.x);
            const float n2y = __fmaf_rn(Bv.y, Bv.y, OY.y * OY.y);
            const float dnx = (Cv.x + SY.x) + 1e-5f;
            const float dny = (Cv.y + SY.y) + 1e-5f;
            float2 o;
            o.x = __fdividef(2.0f * sqrtf(n2x), dnx);
            o.y = __fdividef(2.0f * sqrtf(n2y), dny);
            *reinterpret_cast<float2*>(obase + (size_t)h * RS) = o;
        }
    };

    // Warmup: fill window with rows h0-5 .. h0+4 (no emit)
#pragma unroll
    for (int i = 0; i < 10; ++i) step(h0 - 5 + i, false);
    // Main: each step ingests row h0+5+i and emits output row h0+i
#pragma unroll 11
    for (int i = 0; i < HSr; ++i) step(h0 + 5 + i, true);
}

__global__ __launch_bounds__(THREADS)
void curv_kernel(const float* __restrict__ in, float* __restrict__ out) {
    const int strip = blockIdx.x;
    if (strip == 0 || strip == NSTRIP - 1) {
        run_strip<false>(in, out, strip);
    } else {
        run_strip<true>(in, out, strip);
    }
}

}  // namespace

extern "C" void kernel_launch(void* const* d_in, const int* in_sizes, int n_in,
                              void* d_out, int out_size) {
    const float* in = (const float*)d_in[0];
    float* out = (float*)d_out;
    dim3 grid(NSTRIP, Hd / HSr, Bd);
    curv_kernel<<<grid, THREADS>>>(in, out);
}

// round 2
// speedup vs baseline: 2.2799x; 2.2799x over previous
#include <cuda_runtime.h>
#include <math.h>

namespace {

constexpr int Hd = 512;
constexpr int Wd = 512;
constexpr int Cd = 8;
constexpr int Bd = 16;
constexpr int NSTRIP = 8;            // W strips
constexpr int TWp = Wd / NSTRIP;     // 64 pixels per strip
constexpr int HSr = 64;              // output rows per block
constexpr int RS = Wd * Cd;          // 4096 floats per image row
constexpr int THREADS = TWp * Cd / 2;  // 256 threads: one float2 column each

// smem rings: 3 rings x 11 slots x THREADS float2 (private per-thread columns)
constexpr int RING_SLOT = THREADS;       // float2 per slot
constexpr int RING_SZ   = 11 * RING_SLOT;
constexpr int SMEM_BYTES = 3 * RING_SZ * (int)sizeof(float2);  // 67584

template <bool INTERIOR>
__device__ __forceinline__ void run_strip(const float* __restrict__ in,
                                          float* __restrict__ out,
                                          int strip, float2* __restrict__ ring) {
    const int t  = threadIdx.x;
    const int p  = t >> 2;   // pixel within strip (0..63)
    const int c2 = t & 3;    // float2 slot within channels (0..3)
    const int w  = strip * TWp + p;
    const int h0 = blockIdx.y * HSr;
    const int b  = blockIdx.z;

    const float* colbase = in  + (size_t)b * Hd * RS + w * Cd + c2 * 2;
    float*       obase   = out + (size_t)b * Hd * RS + w * Cd + c2 * 2;

    float2* __restrict__ rR = ring + t;
    float2* __restrict__ rT = ring + RING_SZ + t;
    float2* __restrict__ rU = ring + 2 * RING_SZ + t;

    // Zero-init this thread's ring column (entries "i-11" for i<11 must be 0).
    const float2 z2 = make_float2(0.f, 0.f);
#pragma unroll
    for (int s = 0; s < 11; ++s) {
        rR[s * RING_SLOT] = z2;
        rT[s * RING_SLOT] = z2;
        rU[s * RING_SLOT] = z2;
    }
    // No __syncthreads needed: smem columns are strictly per-thread private.

    // Boundary (w-edge) masks + clamped offsets. Interior: compile-time.
    float msk[11];
    int   off[11];
    if (!INTERIOR) {
#pragma unroll
        for (int k = 0; k < 11; ++k) {
            const int ww = w + (k - 5);
            const bool ok = (ww >= 0) && (ww < Wd);
            msk[k] = ok ? 1.0f : 0.0f;
            off[k] = ok ? (k - 5) * Cd : 0;
        }
    }

    // Sliding vertical sums over the current 11-row window:
    // A = sum R, Bv = sum dh*R, Cv = sum dh^2*R, OY = sum T, SY = sum U
    float2 A  = z2, Bv = z2, Cv = z2, OY = z2, SY = z2;

    int slot = 0;  // ring slot; entry i-11 lives at the same slot as entry i

    auto step = [&](int hin, bool emit) {
        float2 Rn = z2, Tn = z2, Un = z2;
        if (hin >= 0 && hin < Hd) {
            const float* rp = colbase + (size_t)hin * RS;
#pragma unroll
            for (int k = 0; k < 11; ++k) {
                const float dw  = (float)(k - 5);
                const float dw2 = dw * dw;
                const int   o   = INTERIOR ? (k - 5) * Cd : off[k];
                float2 v = *reinterpret_cast<const float2*>(rp + o);
                float2 vm;
                if (INTERIOR) {
                    vm = v;
                } else {
                    vm.x = v.x * msk[k];
                    vm.y = v.y * msk[k];
                }
                Rn.x += vm.x;
                Rn.y += vm.y;
                if (k != 5) {  // dw == 0 contributes nothing to T/U
                    Tn.x = __fmaf_rn(vm.x, dw,  Tn.x);
                    Tn.y = __fmaf_rn(vm.y, dw,  Tn.y);
                    Un.x = __fmaf_rn(vm.x, dw2, Un.x);
                    Un.y = __fmaf_rn(vm.y, dw2, Un.y);
                }
            }
        }

        // Oldest ring entries (row hin-11, leaving the window) — read, then
        // overwrite the same slot with the new entries.
        const int so = slot * RING_SLOT;
        const float2 Ro = rR[so];
        const float2 To = rT[so];
        const float2 Uo = rU[so];
        rR[so] = Rn;
        rT[so] = Tn;
        rU[so] = Un;
        slot = (slot == 10) ? 0 : slot + 1;

        // Exact incremental slide (uses OLD A, Bv):
        //   C' = C - 2B + A - 36*R_old + 25*R_new
        //   B' = B - A + 6*R_old + 5*R_new
        //   A' = A - R_old + R_new
        float2 Cn, Bn, An;
        Cn.x = __fmaf_rn(Bv.x, -2.f, Cv.x) + A.x;
        Cn.x = __fmaf_rn(Ro.x, -36.f, Cn.x);
        Cn.x = __fmaf_rn(Rn.x,  25.f, Cn.x);
        Cn.y = __fmaf_rn(Bv.y, -2.f, Cv.y) + A.y;
        Cn.y = __fmaf_rn(Ro.y, -36.f, Cn.y);
        Cn.y = __fmaf_rn(Rn.y,  25.f, Cn.y);

        Bn.x = Bv.x - A.x;
        Bn.x = __fmaf_rn(Ro.x, 6.f, Bn.x);
        Bn.x = __fmaf_rn(Rn.x, 5.f, Bn.x);
        Bn.y = Bv.y - A.y;
        Bn.y = __fmaf_rn(Ro.y, 6.f, Bn.y);
        Bn.y = __fmaf_rn(Rn.y, 5.f, Bn.y);

        An.x = (A.x - Ro.x) + Rn.x;
        An.y = (A.y - Ro.y) + Rn.y;

        OY.x += Tn.x - To.x;
        OY.y += Tn.y - To.y;
        SY.x += Un.x - Uo.x;
        SY.y += Un.y - Uo.y;

        A = An; Bv = Bn; Cv = Cn;

        if (emit) {
            const int h = hin - 5;
            const float n2x = __fmaf_rn(Bv.x, Bv.x, OY.x * OY.x);
            const float n2y = __fmaf_rn(Bv.y, Bv.y, OY.y * OY.y);
            const float dnx = (Cv.x + SY.x) + 1e-5f;
            const float dny = (Cv.y + SY.y) + 1e-5f;
            float2 o;
            o.x = __fdividef(2.0f * sqrtf(n2x), dnx);
            o.y = __fdividef(2.0f * sqrtf(n2y), dny);
            *reinterpret_cast<float2*>(obase + (size_t)h * RS) = o;
        }
    };

    // Warmup: fill window with rows h0-5 .. h0+4 (no emit)
#pragma unroll
    for (int i = 0; i < 10; ++i) step(h0 - 5 + i, false);
    // Main: each step ingests row h0+5+i and emits output row h0+i
    for (int i = 0; i < HSr; ++i) step(h0 + 5 + i, true);
}

__global__ __launch_bounds__(THREADS, 3)
void curv_kernel(const float* __restrict__ in, float* __restrict__ out) {
    extern __shared__ float2 ring[];
    const int strip = blockIdx.x;
    if (strip == 0 || strip == NSTRIP - 1) {
        run_strip<false>(in, out, strip, ring);
    } else {
        run_strip<true>(in, out, strip, ring);
    }
}

}  // namespace

extern "C" void kernel_launch(void* const* d_in, const int* in_sizes, int n_in,
                              void* d_out, int out_size) {
    const float* in = (const float*)d_in[0];
    float* out = (float*)d_out;
    cudaFuncSetAttribute(curv_kernel, cudaFuncAttributeMaxDynamicSharedMemorySize,
                         SMEM_BYTES);
    dim3 grid(NSTRIP, Hd / HSr, Bd);
    curv_kernel<<<grid, THREADS, SMEM_BYTES>>>(in, out);
}